// round 14
// baseline (speedup 1.0000x reference)
#include <cuda_runtime.h>

#define FF 39
#define EE 16
#define DD 16
#define IPB 6
#define NT  128
#define TPI 20          // threads per item: 10 row-groups x 2 heads
#define NRG 10
#define RPT 4           // rows per attention thread (last group has 3)

typedef unsigned long long u64;
union F4U { float4 f; u64 u[2]; };

__constant__ float4 cW[4][16][4];      // [mat][col j][p4] packed for fma2
__device__ float4 gWstage[256];

__device__ __forceinline__ u64 pk2(float a, float b){
    u64 r; asm("mov.b64 %0,{%1,%2};":"=l"(r):"f"(a),"f"(b)); return r;
}
__device__ __forceinline__ float hadd(u64 v){
    float a,b; asm("mov.b64 {%0,%1},%2;":"=f"(a),"=f"(b):"l"(v)); return a+b;
}
__device__ __forceinline__ void fma2(u64 &acc, u64 a, u64 b){
    asm("fma.rn.f32x2 %0,%1,%2,%0;":"+l"(acc):"l"(a),"l"(b));
}
__device__ __forceinline__ float frcp(float x){
    float r; asm("rcp.approx.f32 %0,%1;":"=f"(r):"f"(x)); return r;
}

__global__ void repack_kernel(const float* __restrict__ Wq, const float* __restrict__ Wk,
                              const float* __restrict__ Wv, const float* __restrict__ Wr)
{
    int idx = threadIdx.x;                  // 0..255 -> [m][j][p4]
    int m = idx >> 6, rem = idx & 63, j = rem >> 2, p4 = rem & 3;
    const float* W = (m==0)?Wq:(m==1)?Wk:(m==2)?Wv:Wr;
    float4 w;
    w.x = W[(4*p4+0)*DD + j];
    w.y = W[(4*p4+1)*DD + j];
    w.z = W[(4*p4+2)*DD + j];
    w.w = W[(4*p4+3)*DD + j];
    gWstage[idx] = w;
}

__global__ __launch_bounds__(NT) void attn_kernel(
    const float* __restrict__ x, float* __restrict__ out, int B)
{
    __shared__ F4U sK[IPB][4][41];     // [item][colGroup][row]; 41: disjoint bank quads
    __shared__ F4U sV[IPB][4][41];
    __shared__ F4U sQ[IPB][4][41];

    int tid  = threadIdx.x;
    int il   = tid / TPI;
    int tpos = tid - il*TPI;
    int ig   = blockIdx.x * IPB + il;
    bool active = (tid < TPI*IPB) && (ig < B);

    // ---------------- projection phase: rows 2*tpos, 2*tpos+1 ----------------
    int f0p = 2*tpos;
    bool has1 = (f0p + 1 < FF);
    if (active) {
        u64 xp0[8], xp1[8];
        const F4U* xr = (const F4U*)(x + ((size_t)ig*FF + f0p)*EE);
        #pragma unroll
        for (int i = 0; i < 4; i++) { F4U t = xr[i]; xp0[2*i]=t.u[0]; xp0[2*i+1]=t.u[1]; }
        if (has1) {
            #pragma unroll
            for (int i = 0; i < 4; i++) { F4U t = xr[4+i]; xp1[2*i]=t.u[0]; xp1[2*i+1]=t.u[1]; }
        } else {
            #pragma unroll
            for (int i = 0; i < 8; i++) xp1[i] = 0;
        }

        float* ro0 = out + ((size_t)ig*FF + f0p)*DD;
        float* ro1 = ro0 + DD;
        #pragma unroll
        for (int pp = 0; pp < 4; pp++) {
            float cq0[4],ck0[4],cv0[4],cr0[4], cq1[4],ck1[4],cv1[4],cr1[4];
            #pragma unroll
            for (int sc = 0; sc < 4; sc++) {
                int j = pp*4 + sc;
                u64 aq0=0,ak0=0,av0=0,ar0=0, aq1=0,ak1=0,av1=0,ar1=0;
                #pragma unroll
                for (int p4 = 0; p4 < 4; p4++) {
                    F4U wq, wk, wv, wr;
                    wq.f = cW[0][j][p4]; wk.f = cW[1][j][p4];
                    wv.f = cW[2][j][p4]; wr.f = cW[3][j][p4];
                    u64 xa0 = xp0[2*p4], xb0 = xp0[2*p4+1];
                    u64 xa1 = xp1[2*p4], xb1 = xp1[2*p4+1];
                    fma2(aq0, xa0, wq.u[0]); fma2(aq0, xb0, wq.u[1]);
                    fma2(ak0, xa0, wk.u[0]); fma2(ak0, xb0, wk.u[1]);
                    fma2(av0, xa0, wv.u[0]); fma2(av0, xb0, wv.u[1]);
                    fma2(ar0, xa0, wr.u[0]); fma2(ar0, xb0, wr.u[1]);
                    fma2(aq1, xa1, wq.u[0]); fma2(aq1, xb1, wq.u[1]);
                    fma2(ak1, xa1, wk.u[0]); fma2(ak1, xb1, wk.u[1]);
                    fma2(av1, xa1, wv.u[0]); fma2(av1, xb1, wv.u[1]);
                    fma2(ar1, xa1, wr.u[0]); fma2(ar1, xb1, wr.u[1]);
                }
                cq0[sc]=hadd(aq0); ck0[sc]=hadd(ak0); cv0[sc]=hadd(av0); cr0[sc]=hadd(ar0);
                cq1[sc]=hadd(aq1); ck1[sc]=hadd(ak1); cv1[sc]=hadd(av1); cr1[sc]=hadd(ar1);
            }
            F4U qq0; qq0.f = make_float4(cq0[0],cq0[1],cq0[2],cq0[3]);
            F4U kk0; kk0.f = make_float4(ck0[0],ck0[1],ck0[2],ck0[3]);
            F4U vv0; vv0.f = make_float4(cv0[0],cv0[1],cv0[2],cv0[3]);
            sQ[il][pp][f0p] = qq0;
            sK[il][pp][f0p] = kk0;
            sV[il][pp][f0p] = vv0;
            ((float4*)ro0)[pp] = make_float4(cr0[0],cr0[1],cr0[2],cr0[3]);  // park residual
            if (has1) {
                F4U qq1; qq1.f = make_float4(cq1[0],cq1[1],cq1[2],cq1[3]);
                F4U kk1; kk1.f = make_float4(ck1[0],ck1[1],ck1[2],ck1[3]);
                F4U vv1; vv1.f = make_float4(cv1[0],cv1[1],cv1[2],cv1[3]);
                sQ[il][pp][f0p+1] = qq1;
                sK[il][pp][f0p+1] = kk1;
                sV[il][pp][f0p+1] = vv1;
                ((float4*)ro1)[pp] = make_float4(cr1[0],cr1[1],cr1[2],cr1[3]);
            }
        }
    }
    __syncthreads();

    // ---------------- attention phase: thread = (head h, rows 4*rg..) ----------------
    if (active) {
        int h   = tpos / NRG;          // 0,1
        int rg  = tpos - h*NRG;        // 0..9
        int fa  = rg * RPT;
        int nr  = (FF - fa < RPT) ? (FF - fa) : RPT;   // 3 for rg=9
        int cg0 = 2*h, cg1 = 2*h + 1;

        u64 q[RPT][4];
        #pragma unroll
        for (int r = 0; r < RPT; r++) {
            int fr = fa + r; if (fr > FF-1) fr = FF-1;   // clamp: dup row 38, discarded
            F4U a = sQ[il][cg0][fr];
            F4U b = sQ[il][cg1][fr];
            q[r][0]=a.u[0]; q[r][1]=a.u[1]; q[r][2]=b.u[0]; q[r][3]=b.u[1];
        }

        u64 o[RPT][4];
        float s[RPT];
        #pragma unroll
        for (int r = 0; r < RPT; r++) {
            s[r] = 0.f;
            #pragma unroll
            for (int i = 0; i < 4; i++) o[r][i] = 0;
        }

        #pragma unroll 3
        for (int g = 0; g < FF; g++) {
            F4U k0 = sK[il][cg0][g], k1 = sK[il][cg1][g];
            F4U v0 = sV[il][cg0][g], v1 = sV[il][cg1][g];
            #pragma unroll
            for (int r = 0; r < RPT; r++) {
                u64 acc = 0;
                fma2(acc, q[r][0], k0.u[0]);
                fma2(acc, q[r][1], k0.u[1]);
                fma2(acc, q[r][2], k1.u[0]);
                fma2(acc, q[r][3], k1.u[1]);
                float e = __expf(hadd(acc));     // max-free: |score| small by construction
                s[r] += e;
                u64 e2 = pk2(e, e);
                fma2(o[r][0], e2, v0.u[0]);
                fma2(o[r][1], e2, v0.u[1]);
                fma2(o[r][2], e2, v1.u[0]);
                fma2(o[r][3], e2, v1.u[1]);
            }
        }

        #pragma unroll
        for (int r = 0; r < RPT; r++) {
            if (r < nr) {
                float ri = frcp(s[r]);
                float* ro = out + ((size_t)ig*FF + fa + r)*DD + 8*h;
                float4 rr0 = ((const float4*)ro)[0];
                float4 rr1 = ((const float4*)ro)[1];
                float a,b,c,d;
                asm("mov.b64 {%0,%1},%2;":"=f"(a),"=f"(b):"l"(o[r][0]));
                asm("mov.b64 {%0,%1},%2;":"=f"(c),"=f"(d):"l"(o[r][1]));
                float4 w0;
                w0.x = fmaxf(fmaf(a, ri, rr0.x), 0.f);
                w0.y = fmaxf(fmaf(b, ri, rr0.y), 0.f);
                w0.z = fmaxf(fmaf(c, ri, rr0.z), 0.f);
                w0.w = fmaxf(fmaf(d, ri, rr0.w), 0.f);
                asm("mov.b64 {%0,%1},%2;":"=f"(a),"=f"(b):"l"(o[r][2]));
                asm("mov.b64 {%0,%1},%2;":"=f"(c),"=f"(d):"l"(o[r][3]));
                float4 w1;
                w1.x = fmaxf(fmaf(a, ri, rr1.x), 0.f);
                w1.y = fmaxf(fmaf(b, ri, rr1.y), 0.f);
                w1.z = fmaxf(fmaf(c, ri, rr1.z), 0.f);
                w1.w = fmaxf(fmaf(d, ri, rr1.w), 0.f);
                ((float4*)ro)[0] = w0;
                ((float4*)ro)[1] = w1;
            }
        }
    }
}

extern "C" void kernel_launch(void* const* d_in, const int* in_sizes, int n_in,
                              void* d_out, int out_size)
{
    const float* x  = (const float*)d_in[0];
    const float* Wq = (const float*)d_in[1];
    const float* Wk = (const float*)d_in[2];
    const float* Wv = (const float*)d_in[3];
    const float* Wr = (const float*)d_in[4];
    float* out = (float*)d_out;
    int B = in_sizes[0] / (FF*EE);

    repack_kernel<<<1, 256>>>(Wq, Wk, Wv, Wr);
    void* stage_ptr = nullptr;
    cudaGetSymbolAddress(&stage_ptr, gWstage);
    cudaMemcpyToSymbolAsync(cW, stage_ptr, 256*sizeof(float4), 0,
                            cudaMemcpyDeviceToDevice, 0);

    int nb = (B + IPB - 1) / IPB;
    attn_kernel<<<nb, NT>>>(x, out, B);
}

// round 15
// speedup vs baseline: 1.3164x; 1.3164x over previous
#include <cuda_runtime.h>

#define FF 39
#define EE 16
#define DD 16
#define IPB 4
#define NT  96          // 4 items x 20 threads = 80 active; all 96 help stage/copy
#define TPI 20
#define NRG 10
#define RPT 4

typedef unsigned long long u64;
union F4U { float4 f; u64 u[2]; };

__device__ __forceinline__ u64 pk2(float a, float b){
    u64 r; asm("mov.b64 %0,{%1,%2};":"=l"(r):"f"(a),"f"(b)); return r;
}
__device__ __forceinline__ float hadd(u64 v){
    float a,b; asm("mov.b64 {%0,%1},%2;":"=f"(a),"=f"(b):"l"(v)); return a+b;
}
__device__ __forceinline__ void fma2(u64 &acc, u64 a, u64 b){
    asm("fma.rn.f32x2 %0,%1,%2,%0;":"+l"(acc):"l"(a),"l"(b));
}
__device__ __forceinline__ float frcp(float x){
    float r; asm("rcp.approx.f32 %0,%1;":"=f"(r):"f"(x)); return r;
}

__global__ __launch_bounds__(NT) void attn_kernel(
    const float* __restrict__ x, const float* __restrict__ Wq,
    const float* __restrict__ Wk, const float* __restrict__ Wv,
    const float* __restrict__ Wr, float* __restrict__ out, int B)
{
    __shared__ F4U sW[4][16][4];       // 4 KB, broadcast LDS -> direct FFMA2 operands
    __shared__ F4U sQ[IPB][4][41];     // [item][colGroup][row], 41: bank-disjoint
    __shared__ F4U sK[IPB][4][41];
    __shared__ F4U sV[IPB][4][41];
    __shared__ F4U sR[IPB][4][41];     // x-stage -> residual -> final result

    int tid = threadIdx.x;
    int ib0 = blockIdx.x * IPB;

    // ---- weights -> smem (256 float4, once per block) ----
    {
        const float* Ws[4] = {Wq, Wk, Wv, Wr};
        for (int idx = tid; idx < 256; idx += NT) {
            int m = idx >> 6, rem = idx & 63, j = rem >> 2, p4 = rem & 3;
            const float* W = Ws[m];
            float4 w;
            w.x = W[(4*p4+0)*DD + j];
            w.y = W[(4*p4+1)*DD + j];
            w.z = W[(4*p4+2)*DD + j];
            w.w = W[(4*p4+3)*DD + j];
            sW[m][j][p4].f = w;
        }
    }
    // ---- x: cooperative COALESCED load into sR ----
    {
        const float4* xb = (const float4*)(x + (size_t)ib0*FF*EE);
        int total = IPB*FF*4;
        int avail = (B - ib0) * FF * 4; if (avail < total) total = avail;
        for (int idx = tid; idx < total; idx += NT) {
            int il2 = idx / (FF*4);
            int rem = idx - il2*(FF*4);
            int row = rem >> 2, p = rem & 3;
            F4U t; t.f = xb[idx];
            sR[il2][p][row] = t;
        }
    }
    __syncthreads();

    int il   = tid / TPI;
    int tpos = tid - il*TPI;
    int ig   = ib0 + il;
    bool active = (tid < TPI*IPB) && (ig < B);

    int f0p = 2*tpos;
    bool has1 = (f0p + 1 < FF);

    // ---- x rows from smem into regs ----
    u64 xp0[8], xp1[8];
    if (active) {
        #pragma unroll
        for (int p = 0; p < 4; p++) { F4U t = sR[il][p][f0p]; xp0[2*p]=t.u[0]; xp0[2*p+1]=t.u[1]; }
        if (has1) {
            #pragma unroll
            for (int p = 0; p < 4; p++) { F4U t = sR[il][p][f0p+1]; xp1[2*p]=t.u[0]; xp1[2*p+1]=t.u[1]; }
        } else {
            #pragma unroll
            for (int i = 0; i < 8; i++) xp1[i] = 0;
        }
    }
    __syncthreads();   // all x reads complete before residual overwrites sR

    // ---- projection: rows f0p, f0p+1 ----
    if (active) {
        #pragma unroll
        for (int pp = 0; pp < 4; pp++) {
            float cq0[4],ck0[4],cv0[4],cr0[4], cq1[4],ck1[4],cv1[4],cr1[4];
            #pragma unroll
            for (int sc = 0; sc < 4; sc++) {
                int j = pp*4 + sc;
                u64 aq0=0,ak0=0,av0=0,ar0=0, aq1=0,ak1=0,av1=0,ar1=0;
                #pragma unroll
                for (int p4 = 0; p4 < 4; p4++) {
                    F4U wq = sW[0][j][p4], wk = sW[1][j][p4];
                    F4U wv = sW[2][j][p4], wr = sW[3][j][p4];
                    u64 xa0 = xp0[2*p4], xb0 = xp0[2*p4+1];
                    u64 xa1 = xp1[2*p4], xb1 = xp1[2*p4+1];
                    fma2(aq0, xa0, wq.u[0]); fma2(aq0, xb0, wq.u[1]);
                    fma2(ak0, xa0, wk.u[0]); fma2(ak0, xb0, wk.u[1]);
                    fma2(av0, xa0, wv.u[0]); fma2(av0, xb0, wv.u[1]);
                    fma2(ar0, xa0, wr.u[0]); fma2(ar0, xb0, wr.u[1]);
                    fma2(aq1, xa1, wq.u[0]); fma2(aq1, xb1, wq.u[1]);
                    fma2(ak1, xa1, wk.u[0]); fma2(ak1, xb1, wk.u[1]);
                    fma2(av1, xa1, wv.u[0]); fma2(av1, xb1, wv.u[1]);
                    fma2(ar1, xa1, wr.u[0]); fma2(ar1, xb1, wr.u[1]);
                }
                cq0[sc]=hadd(aq0); ck0[sc]=hadd(ak0); cv0[sc]=hadd(av0); cr0[sc]=hadd(ar0);
                cq1[sc]=hadd(aq1); ck1[sc]=hadd(ak1); cv1[sc]=hadd(av1); cr1[sc]=hadd(ar1);
            }
            F4U qq0; qq0.f = make_float4(cq0[0],cq0[1],cq0[2],cq0[3]);
            F4U kk0; kk0.f = make_float4(ck0[0],ck0[1],ck0[2],ck0[3]);
            F4U vv0; vv0.f = make_float4(cv0[0],cv0[1],cv0[2],cv0[3]);
            F4U rr0; rr0.f = make_float4(cr0[0],cr0[1],cr0[2],cr0[3]);
            sQ[il][pp][f0p] = qq0;
            sK[il][pp][f0p] = kk0;
            sV[il][pp][f0p] = vv0;
            sR[il][pp][f0p] = rr0;                    // residual in smem
            if (has1) {
                F4U qq1; qq1.f = make_float4(cq1[0],cq1[1],cq1[2],cq1[3]);
                F4U kk1; kk1.f = make_float4(ck1[0],ck1[1],ck1[2],ck1[3]);
                F4U vv1; vv1.f = make_float4(cv1[0],cv1[1],cv1[2],cv1[3]);
                F4U rr1; rr1.f = make_float4(cr1[0],cr1[1],cr1[2],cr1[3]);
                sQ[il][pp][f0p+1] = qq1;
                sK[il][pp][f0p+1] = kk1;
                sV[il][pp][f0p+1] = vv1;
                sR[il][pp][f0p+1] = rr1;
            }
        }
    }
    __syncthreads();

    // ---- attention: thread = (head h, rows RPT*rg ..) ----
    if (active) {
        int h   = tpos / NRG;          // 0,1
        int rg  = tpos - h*NRG;        // 0..9
        int fa  = rg * RPT;
        int nr  = (FF - fa < RPT) ? (FF - fa) : RPT;
        int cg0 = 2*h, cg1 = 2*h + 1;

        u64 q[RPT][4];
        #pragma unroll
        for (int r = 0; r < RPT; r++) {
            int fr = fa + r; if (fr > FF-1) fr = FF-1;
            F4U a = sQ[il][cg0][fr];
            F4U b = sQ[il][cg1][fr];
            q[r][0]=a.u[0]; q[r][1]=a.u[1]; q[r][2]=b.u[0]; q[r][3]=b.u[1];
        }

        u64 o[RPT][4];
        float s[RPT];
        #pragma unroll
        for (int r = 0; r < RPT; r++) {
            s[r] = 0.f;
            #pragma unroll
            for (int i = 0; i < 4; i++) o[r][i] = 0;
        }

        #pragma unroll 3
        for (int g = 0; g < FF; g++) {
            F4U k0 = sK[il][cg0][g], k1 = sK[il][cg1][g];
            F4U v0 = sV[il][cg0][g], v1 = sV[il][cg1][g];
            #pragma unroll
            for (int r = 0; r < RPT; r++) {
                u64 acc = 0;
                fma2(acc, q[r][0], k0.u[0]);
                fma2(acc, q[r][1], k0.u[1]);
                fma2(acc, q[r][2], k1.u[0]);
                fma2(acc, q[r][3], k1.u[1]);
                float e = __expf(hadd(acc));    // max-free softmax: |score| small
                s[r] += e;
                u64 e2 = pk2(e, e);
                fma2(o[r][0], e2, v0.u[0]);
                fma2(o[r][1], e2, v0.u[1]);
                fma2(o[r][2], e2, v1.u[0]);
                fma2(o[r][3], e2, v1.u[1]);
            }
        }

        #pragma unroll
        for (int r = 0; r < RPT; r++) {
            if (r < nr) {
                float ri = frcp(s[r]);
                int fr = fa + r;
                F4U rr0 = sR[il][cg0][fr];
                F4U rr1 = sR[il][cg1][fr];
                float a,b,c,d;
                asm("mov.b64 {%0,%1},%2;":"=f"(a),"=f"(b):"l"(o[r][0]));
                asm("mov.b64 {%0,%1},%2;":"=f"(c),"=f"(d):"l"(o[r][1]));
                F4U w0;
                w0.f.x = fmaxf(fmaf(a, ri, rr0.f.x), 0.f);
                w0.f.y = fmaxf(fmaf(b, ri, rr0.f.y), 0.f);
                w0.f.z = fmaxf(fmaf(c, ri, rr0.f.z), 0.f);
                w0.f.w = fmaxf(fmaf(d, ri, rr0.f.w), 0.f);
                asm("mov.b64 {%0,%1},%2;":"=f"(a),"=f"(b):"l"(o[r][2]));
                asm("mov.b64 {%0,%1},%2;":"=f"(c),"=f"(d):"l"(o[r][3]));
                F4U w1;
                w1.f.x = fmaxf(fmaf(a, ri, rr1.f.x), 0.f);
                w1.f.y = fmaxf(fmaf(b, ri, rr1.f.y), 0.f);
                w1.f.z = fmaxf(fmaf(c, ri, rr1.f.z), 0.f);
                w1.f.w = fmaxf(fmaf(d, ri, rr1.f.w), 0.f);
                sR[il][cg0][fr] = w0;          // stage final result (single owner)
                sR[il][cg1][fr] = w1;
            }
        }
    }
    __syncthreads();

    // ---- final: cooperative COALESCED store ----
    {
        float4* ob = (float4*)(out + (size_t)ib0*FF*DD);
        int total = IPB*FF*4;
        int avail = (B - ib0) * FF * 4; if (avail < total) total = avail;
        for (int idx = tid; idx < total; idx += NT) {
            int il2 = idx / (FF*4);
            int rem = idx - il2*(FF*4);
            int row = rem >> 2, p = rem & 3;
            ob[idx] = sR[il2][p][row].f;
        }
    }
}

extern "C" void kernel_launch(void* const* d_in, const int* in_sizes, int n_in,
                              void* d_out, int out_size)
{
    const float* x  = (const float*)d_in[0];
    const float* Wq = (const float*)d_in[1];
    const float* Wk = (const float*)d_in[2];
    const float* Wv = (const float*)d_in[3];
    const float* Wr = (const float*)d_in[4];
    float* out = (float*)d_out;
    int B = in_sizes[0] / (FF*EE);
    int nb = (B + IPB - 1) / IPB;
    attn_kernel<<<nb, NT>>>(x, Wq, Wk, Wv, Wr, out, B);
}